// round 4
// baseline (speedup 1.0000x reference)
#include <cuda_runtime.h>
#include <math_constants.h>

// Problem constants (fixed by the reference: B=8, N=4096, D=2)
#define BQ      8
#define NPTS    4096
#define THREADS 256
#define IPT     2                   // query points per thread (packed in f32x2 lanes)
#define TILE    (THREADS * IPT)     // 512 queries per block
#define NTILES  (NPTS / TILE)       // 8
#define NBLOCKS (NTILES * BQ * 2)   // 128
#define CHUNK   1024                // reference points staged per shared pass
#define NCHUNK  (NPTS / CHUNK)      // 4

__device__ float g_partials[NBLOCKS];
__device__ int   g_counter = 0;     // reset to 0 by the last block each call

// Packed 2xfp32 FMA (SASS FFMA2) — only reachable via PTX fma.rn.f32x2.
__device__ __forceinline__ unsigned long long fma2(unsigned long long a,
                                                   unsigned long long b,
                                                   unsigned long long c) {
    unsigned long long d;
    asm("fma.rn.f32x2 %0, %1, %2, %3;" : "=l"(d) : "l"(a), "l"(b), "l"(c));
    return d;
}
__device__ __forceinline__ unsigned long long pk2(float lo, float hi) {
    unsigned long long r;
    asm("mov.b64 %0, {%1, %2};" : "=l"(r) : "f"(lo), "f"(hi));
    return r;
}
__device__ __forceinline__ void unpk2(unsigned long long v, float& lo, float& hi) {
    asm("mov.b64 {%0, %1}, %2;" : "=f"(lo), "=f"(hi) : "l"(v));
}

// One block: (tile of 512 query points) x (batch) x (direction).
// dir 0: queries = y_true, reference set = y_pred  (also fuses EMD terms)
// dir 1: queries = y_pred, reference set = y_true
__global__ __launch_bounds__(THREADS, 1)
void chamfer_kernel(const float* __restrict__ yt, const float* __restrict__ yp,
                    float* __restrict__ out) {
    __shared__ float4 sXY[CHUNK];   // (px, px, py, py) duplicated : 16 KB
    __shared__ float2 sPP[CHUNK];   // (pp, pp) duplicated         : 8 KB
    __shared__ float  red[THREADS]; // block reduction             : 1 KB
    __shared__ bool   isLast;

    const int tid = threadIdx.x;
    const int b   = blockIdx.y;
    const int dir = blockIdx.z;
    const float* srcBase = (dir == 0 ? yt : yp) + (size_t)b * NPTS * 2; // queries
    const float* refBase = (dir == 0 ? yp : yt) + (size_t)b * NPTS * 2; // reference set

    const int i0 = blockIdx.x * TILE + tid;

    // Pack this thread's two query points into the two f32 lanes.
    const float2 q0 = reinterpret_cast<const float2*>(srcBase)[i0];
    const float2 q1 = reinterpret_cast<const float2*>(srcBase)[i0 + THREADS];
    const unsigned long long ax2 = pk2(-2.0f * q0.x, -2.0f * q1.x);
    const unsigned long long ay2 = pk2(-2.0f * q0.y, -2.0f * q1.y);
    const float xx0 = fmaf(q0.x, q0.x, q0.y * q0.y);
    const float xx1 = fmaf(q1.x, q1.x, q1.y * q1.y);
    float best0 = CUDART_INF_F, best1 = CUDART_INF_F;

    const ulonglong2*         sXY64 = reinterpret_cast<const ulonglong2*>(sXY);
    const unsigned long long* sPP64 = reinterpret_cast<const unsigned long long*>(sPP);

    for (int c = 0; c < NCHUNK; c++) {
        __syncthreads();
        // cooperative stage: duplicated layout, pp precomputed
        for (int j = tid; j < CHUNK; j += THREADS) {
            const float2 p = reinterpret_cast<const float2*>(refBase)[c * CHUNK + j];
            const float pp = fmaf(p.x, p.x, p.y * p.y);
            sXY[j] = make_float4(p.x, p.x, p.y, p.y);
            sPP[j] = make_float2(pp, pp);
        }
        __syncthreads();

#pragma unroll 8
        for (int j = 0; j < CHUNK; j++) {
            const ulonglong2 xy = sXY64[j];           // LDS.128 broadcast: (px,px),(py,py)
            const unsigned long long pp2 = sPP64[j];  // LDS.64  broadcast: (pp,pp)
            unsigned long long t2 = fma2(ax2, xy.x, pp2);   // pp - 2*x*px   (both queries)
            t2 = fma2(ay2, xy.y, t2);                       //    - 2*y*py
            float t0, t1;
            unpk2(t2, t0, t1);                              // register-pair split (free)
            best0 = fminf(best0, t0);
            best1 = fminf(best1, t1);
        }
    }

    // NN squared distance: max(xx + best, 0); clamp commutes with min.
    float local = fmaxf(xx0 + best0, 0.0f) + fmaxf(xx1 + best1, 0.0f);
    local *= (1.0f / BQ);   // mean over batch of per-batch sums

    if (dir == 0) {
        // Fused EMD approximation: cumsum over D=2 -> (t0-p0)^2 + (t0+t1-p0-p1)^2
        const float* tb = yt + (size_t)b * NPTS * 2;
        const float* pb = yp + (size_t)b * NPTS * 2;
        float e = 0.0f;
#pragma unroll
        for (int k = 0; k < IPT; k++) {
            const int i = i0 + k * THREADS;
            const float2 t = reinterpret_cast<const float2*>(tb)[i];
            const float2 p = reinterpret_cast<const float2*>(pb)[i];
            const float d0 = t.x - p.x;
            const float d1 = (t.x + t.y) - (p.x + p.y);
            e = fmaf(d0, d0, e);
            e = fmaf(d1, d1, e);
        }
        local += e * (1.0f / ((float)BQ * NPTS * 2));
    }

    // Deterministic block tree reduction
    red[tid] = local;
    __syncthreads();
    for (int s = THREADS / 2; s > 0; s >>= 1) {
        if (tid < s) red[tid] += red[tid + s];
        __syncthreads();
    }
    const int bid = (blockIdx.z * gridDim.y + blockIdx.y) * gridDim.x + blockIdx.x;
    if (tid == 0) {
        g_partials[bid] = red[0];
        __threadfence();
        const int c = atomicAdd(&g_counter, 1);
        isLast = (c == NBLOCKS - 1);
    }
    __syncthreads();

    // Last block performs the deterministic fixed-order final sum.
    if (isLast) {
        float v = 0.0f;
        if (tid < NBLOCKS) {
            __threadfence();
            v = *((volatile float*)&g_partials[tid]);
        }
        red[tid] = v;
        __syncthreads();
        for (int s = THREADS / 2; s > 0; s >>= 1) {
            if (tid < s) red[tid] += red[tid + s];
            __syncthreads();
        }
        if (tid == 0) {
            out[0] = red[0];
            g_counter = 0;   // reset for next graph replay
        }
    }
}

extern "C" void kernel_launch(void* const* d_in, const int* in_sizes, int n_in,
                              void* d_out, int out_size) {
    const float* y_true = (const float*)d_in[0];
    const float* y_pred = (const float*)d_in[1];
    float* out = (float*)d_out;

    dim3 grid(NTILES, BQ, 2);
    chamfer_kernel<<<grid, THREADS>>>(y_true, y_pred, out);
}

// round 7
// speedup vs baseline: 2.4383x; 2.4383x over previous
#include <cuda_runtime.h>
#include <math_constants.h>

// Problem constants (fixed by the reference: B=8, N=4096, D=2)
#define BQ       8
#define NPTS     4096
#define THREADS  512                 // 2 half-blocks x 256
#define HALF_T   256
#define TILE     512                 // queries per block (each thread: q and q+256)
#define NTILES   (NPTS / TILE)       // 8
#define NBLOCKS  (NTILES * BQ * 2)   // 128
#define REFS_PER_HALF 2048           // each half-block scans half the reference set
#define CHUNK_PAIRS   512            // ref-pairs staged per chunk (1024 refs)
#define NCHUNK   (REFS_PER_HALF / (2 * CHUNK_PAIRS))  // 2

__device__ float g_partials[NBLOCKS];
__device__ int   g_counter = 0;      // reset by last block each call (graph-replay safe)

// ---- packed f32x2 helpers (SASS FFMA2; ptxas won't emit from C++) ----
__device__ __forceinline__ unsigned long long fma2(unsigned long long a,
                                                   unsigned long long b,
                                                   unsigned long long c) {
    unsigned long long d;
    asm("fma.rn.f32x2 %0, %1, %2, %3;" : "=l"(d) : "l"(a), "l"(b), "l"(c));
    return d;
}
__device__ __forceinline__ unsigned long long pk2(float lo, float hi) {
    unsigned long long r;
    asm("mov.b64 %0, {%1, %2};" : "=l"(r) : "f"(lo), "f"(hi));
    return r;
}
// Register-pair split — free in SASS (ptxas aliases the halves).
__device__ __forceinline__ void unpk2(unsigned long long v, float& lo, float& hi) {
    asm("mov.b64 {%0, %1}, %2;" : "=f"(lo), "=f"(hi) : "l"(v));
}

// One block: (tile of 512 query points) x (batch) x (direction).
// dir 0: queries = y_true, reference set = y_pred  (also fuses EMD terms)
// dir 1: queries = y_pred, reference set = y_true
// Half-block h (threads h*256..h*256+255) scans reference range [h*2048, h*2048+2048).
__global__ __launch_bounds__(THREADS, 1)
void chamfer_kernel(const float* __restrict__ yt, const float* __restrict__ yp,
                    float* __restrict__ out) {
    // Per half-block staging: ref-pairs as (px0,px1,py0,py1) + (pp0,pp1)
    __shared__ float4 sXY[2][CHUNK_PAIRS];   // 16 KB
    __shared__ float2 sPP[2][CHUNK_PAIRS];   //  8 KB
    __shared__ float  sBest[2][TILE];        //  4 KB  per-half per-query best
    __shared__ float  red[THREADS];          //  2 KB
    __shared__ bool   isLast;

    const int tid = threadIdx.x;
    const int h   = tid >> 8;        // half-block id
    const int q   = tid & 255;       // query slot within half
    const int b   = blockIdx.y;
    const int dir = blockIdx.z;
    const float* srcBase = (dir == 0 ? yt : yp) + (size_t)b * NPTS * 2; // queries
    const float* refBase = (dir == 0 ? yp : yt) + (size_t)b * NPTS * 2; // reference set

    const int i0 = blockIdx.x * TILE + q;     // query 0
    const int i1 = i0 + HALF_T;               // query 1

    const float2 q0 = reinterpret_cast<const float2*>(srcBase)[i0];
    const float2 q1 = reinterpret_cast<const float2*>(srcBase)[i1];
    // Query constants duplicated into both f32x2 lanes (registers, once).
    const unsigned long long ax20 = pk2(-2.0f * q0.x, -2.0f * q0.x);
    const unsigned long long ay20 = pk2(-2.0f * q0.y, -2.0f * q0.y);
    const unsigned long long ax21 = pk2(-2.0f * q1.x, -2.0f * q1.x);
    const unsigned long long ay21 = pk2(-2.0f * q1.y, -2.0f * q1.y);
    const float xx0 = fmaf(q0.x, q0.x, q0.y * q0.y);
    const float xx1 = fmaf(q1.x, q1.x, q1.y * q1.y);
    // Scalar best accumulators per lane (even refs / odd refs).
    float b0e = CUDART_INF_F, b0o = CUDART_INF_F;
    float b1e = CUDART_INF_F, b1o = CUDART_INF_F;

    for (int c = 0; c < NCHUNK; c++) {
        __syncthreads();
        // Stage this half's chunk: 512 ref-pairs; 256 threads -> 2 pairs each.
        const float4* refPairs = reinterpret_cast<const float4*>(refBase)
                               + h * (REFS_PER_HALF / 2) + c * CHUNK_PAIRS;
        for (int j = q; j < CHUNK_PAIRS; j += HALF_T) {
            const float4 v = refPairs[j];            // (p0x,p0y,p1x,p1y)
            sXY[h][j] = make_float4(v.x, v.z, v.y, v.w);   // (px0,px1,py0,py1)
            sPP[h][j] = make_float2(fmaf(v.x, v.x, v.y * v.y),
                                    fmaf(v.z, v.z, v.w * v.w));
        }
        __syncthreads();

        const ulonglong2*         xyp = reinterpret_cast<const ulonglong2*>(sXY[h]);
        const unsigned long long* ppp = reinterpret_cast<const unsigned long long*>(sPP[h]);
#pragma unroll 8
        for (int j = 0; j < CHUNK_PAIRS; j++) {
            const ulonglong2 xy         = xyp[j];   // LDS.128 broadcast: (px0,px1),(py0,py1)
            const unsigned long long pp = ppp[j];   // LDS.64  broadcast: (pp0,pp1)

            unsigned long long t0 = fma2(ax20, xy.x, pp);   // q0 vs (ref_e, ref_o)
            t0 = fma2(ay20, xy.y, t0);
            float t0e, t0o; unpk2(t0, t0e, t0o);            // free split
            b0e = fminf(b0e, t0e);
            b0o = fminf(b0o, t0o);

            unsigned long long t1 = fma2(ax21, xy.x, pp);   // q1 vs (ref_e, ref_o)
            t1 = fma2(ay21, xy.y, t1);
            float t1e, t1o; unpk2(t1, t1e, t1o);
            b1e = fminf(b1e, t1e);
            b1o = fminf(b1o, t1o);
        }
    }

    // Reduce packed lanes (even/odd refs) and publish per-half bests.
    sBest[h][q]          = fminf(b0e, b0o);
    sBest[h][q + HALF_T] = fminf(b1e, b1o);
    __syncthreads();

    // Half 0 combines across halves and forms the final per-query terms.
    float local = 0.0f;
    if (h == 0) {
        const float m0 = fminf(sBest[0][q],          sBest[1][q]);
        const float m1 = fminf(sBest[0][q + HALF_T], sBest[1][q + HALF_T]);
        // NN squared distance: max(xx + best, 0); clamp commutes with min.
        local = fmaxf(xx0 + m0, 0.0f) + fmaxf(xx1 + m1, 0.0f);
        local *= (1.0f / BQ);   // mean over batch of per-batch sums

        if (dir == 0) {
            // Fused EMD: cumsum over D=2 -> (t0-p0)^2 + (t0+t1-p0-p1)^2
            const float* tb = yt + (size_t)b * NPTS * 2;
            const float* pb = yp + (size_t)b * NPTS * 2;
            float e = 0.0f;
            const float2 t0v = reinterpret_cast<const float2*>(tb)[i0];
            const float2 p0v = reinterpret_cast<const float2*>(pb)[i0];
            const float2 t1v = reinterpret_cast<const float2*>(tb)[i1];
            const float2 p1v = reinterpret_cast<const float2*>(pb)[i1];
            float d0 = t0v.x - p0v.x;
            float d1 = (t0v.x + t0v.y) - (p0v.x + p0v.y);
            e = fmaf(d0, d0, e); e = fmaf(d1, d1, e);
            d0 = t1v.x - p1v.x;
            d1 = (t1v.x + t1v.y) - (p1v.x + p1v.y);
            e = fmaf(d0, d0, e); e = fmaf(d1, d1, e);
            local += e * (1.0f / ((float)BQ * NPTS * 2));
        }
    }

    // Deterministic block tree reduction over all 512 threads.
    red[tid] = local;
    __syncthreads();
    for (int s = THREADS / 2; s > 0; s >>= 1) {
        if (tid < s) red[tid] += red[tid + s];
        __syncthreads();
    }
    const int bid = (blockIdx.z * gridDim.y + blockIdx.y) * gridDim.x + blockIdx.x;
    if (tid == 0) {
        g_partials[bid] = red[0];
        __threadfence();
        const int c = atomicAdd(&g_counter, 1);
        isLast = (c == NBLOCKS - 1);
    }
    __syncthreads();

    // Last block: deterministic fixed-order final sum of the 128 partials.
    if (isLast) {
        float v = 0.0f;
        if (tid < NBLOCKS) {
            __threadfence();
            v = *((volatile float*)&g_partials[tid]);
        }
        red[tid] = v;
        __syncthreads();
        for (int s = THREADS / 2; s > 0; s >>= 1) {
            if (tid < s) red[tid] += red[tid + s];
            __syncthreads();
        }
        if (tid == 0) {
            out[0] = red[0];
            g_counter = 0;   // reset for next graph replay
        }
    }
}

extern "C" void kernel_launch(void* const* d_in, const int* in_sizes, int n_in,
                              void* d_out, int out_size) {
    const float* y_true = (const float*)d_in[0];
    const float* y_pred = (const float*)d_in[1];
    float* out = (float*)d_out;

    dim3 grid(NTILES, BQ, 2);
    chamfer_kernel<<<grid, THREADS>>>(y_true, y_pred, out);
}

// round 8
// speedup vs baseline: 2.5649x; 1.0519x over previous
#include <cuda_runtime.h>
#include <math_constants.h>

// Problem constants (fixed by the reference: B=8, N=4096, D=2)
#define BQ       8
#define NPTS     4096
#define THREADS  1024                // 4 quarter-blocks x 256
#define QUART_T  256
#define TILE     512                 // queries per block (each thread: q and q+256)
#define NTILES   (NPTS / TILE)       // 8
#define NBLOCKS  (NTILES * BQ * 2)   // 128
#define REFS_PER_QUART 1024          // each quarter scans 1/4 of the reference set
#define CHUNK_PAIRS    256           // ref-pairs staged per chunk (512 refs)
#define NCHUNK   (REFS_PER_QUART / (2 * CHUNK_PAIRS))  // 2

__device__ float g_partials[NBLOCKS];
__device__ int   g_counter = 0;      // reset by last block each call (graph-replay safe)

// ---- packed f32x2 helpers (SASS FFMA2; ptxas won't emit from C++) ----
__device__ __forceinline__ unsigned long long fma2(unsigned long long a,
                                                   unsigned long long b,
                                                   unsigned long long c) {
    unsigned long long d;
    asm("fma.rn.f32x2 %0, %1, %2, %3;" : "=l"(d) : "l"(a), "l"(b), "l"(c));
    return d;
}
__device__ __forceinline__ unsigned long long pk2(float lo, float hi) {
    unsigned long long r;
    asm("mov.b64 %0, {%1, %2};" : "=l"(r) : "f"(lo), "f"(hi));
    return r;
}
// Register-pair split — free in SASS (ptxas aliases the halves).
__device__ __forceinline__ void unpk2(unsigned long long v, float& lo, float& hi) {
    asm("mov.b64 {%0, %1}, %2;" : "=f"(lo), "=f"(hi) : "l"(v));
}

// One block: (tile of 512 query points) x (batch) x (direction).
// dir 0: queries = y_true, reference set = y_pred  (also fuses EMD terms)
// dir 1: queries = y_pred, reference set = y_true
// Quarter h (threads h*256..h*256+255) scans reference range [h*1024, h*1024+1024).
__global__ __launch_bounds__(THREADS, 1)
void chamfer_kernel(const float* __restrict__ yt, const float* __restrict__ yp,
                    float* __restrict__ out) {
    // Per quarter staging: ref-pairs as (px0,px1,py0,py1) + (pp0,pp1)
    __shared__ float4 sXY[4][CHUNK_PAIRS];   // 16 KB
    __shared__ float2 sPP[4][CHUNK_PAIRS];   //  8 KB
    __shared__ float  sBest[4][TILE];        //  8 KB  per-quarter per-query best
    __shared__ float  red[THREADS];          //  4 KB
    __shared__ bool   isLast;

    const int tid = threadIdx.x;
    const int h   = tid >> 8;        // quarter id (0..3)
    const int q   = tid & 255;       // query slot within quarter
    const int b   = blockIdx.y;
    const int dir = blockIdx.z;
    const float* srcBase = (dir == 0 ? yt : yp) + (size_t)b * NPTS * 2; // queries
    const float* refBase = (dir == 0 ? yp : yt) + (size_t)b * NPTS * 2; // reference set

    const int i0 = blockIdx.x * TILE + q;     // query 0
    const int i1 = i0 + QUART_T;              // query 1

    const float2 q0 = reinterpret_cast<const float2*>(srcBase)[i0];
    const float2 q1 = reinterpret_cast<const float2*>(srcBase)[i1];
    // Query constants duplicated into both f32x2 lanes (registers, once).
    const unsigned long long ax20 = pk2(-2.0f * q0.x, -2.0f * q0.x);
    const unsigned long long ay20 = pk2(-2.0f * q0.y, -2.0f * q0.y);
    const unsigned long long ax21 = pk2(-2.0f * q1.x, -2.0f * q1.x);
    const unsigned long long ay21 = pk2(-2.0f * q1.y, -2.0f * q1.y);
    const float xx0 = fmaf(q0.x, q0.x, q0.y * q0.y);
    const float xx1 = fmaf(q1.x, q1.x, q1.y * q1.y);
    // Scalar best accumulators per lane (even refs / odd refs).
    float b0e = CUDART_INF_F, b0o = CUDART_INF_F;
    float b1e = CUDART_INF_F, b1o = CUDART_INF_F;

    for (int c = 0; c < NCHUNK; c++) {
        __syncthreads();
        // Stage this quarter's chunk: 256 ref-pairs; 256 threads -> 1 pair each.
        {
            const float4 v = reinterpret_cast<const float4*>(refBase)
                             [h * (REFS_PER_QUART / 2) + c * CHUNK_PAIRS + q];
            sXY[h][q] = make_float4(v.x, v.z, v.y, v.w);   // (px0,px1,py0,py1)
            sPP[h][q] = make_float2(fmaf(v.x, v.x, v.y * v.y),
                                    fmaf(v.z, v.z, v.w * v.w));
        }
        __syncthreads();

        const ulonglong2*         xyp = reinterpret_cast<const ulonglong2*>(sXY[h]);
        const unsigned long long* ppp = reinterpret_cast<const unsigned long long*>(sPP[h]);
#pragma unroll 4
        for (int j = 0; j < CHUNK_PAIRS; j++) {
            const ulonglong2 xy         = xyp[j];   // LDS.128 broadcast: (px0,px1),(py0,py1)
            const unsigned long long pp = ppp[j];   // LDS.64  broadcast: (pp0,pp1)

            unsigned long long t0 = fma2(ax20, xy.x, pp);   // q0 vs (ref_e, ref_o)
            t0 = fma2(ay20, xy.y, t0);
            float t0e, t0o; unpk2(t0, t0e, t0o);            // free split
            b0e = fminf(b0e, t0e);
            b0o = fminf(b0o, t0o);

            unsigned long long t1 = fma2(ax21, xy.x, pp);   // q1 vs (ref_e, ref_o)
            t1 = fma2(ay21, xy.y, t1);
            float t1e, t1o; unpk2(t1, t1e, t1o);
            b1e = fminf(b1e, t1e);
            b1o = fminf(b1o, t1o);
        }
    }

    // Reduce packed lanes (even/odd refs) and publish per-quarter bests.
    sBest[h][q]           = fminf(b0e, b0o);
    sBest[h][q + QUART_T] = fminf(b1e, b1o);
    __syncthreads();

    // Quarter 0 combines across quarters and forms the final per-query terms.
    float local = 0.0f;
    if (h == 0) {
        const float m0 = fminf(fminf(sBest[0][q],           sBest[1][q]),
                               fminf(sBest[2][q],           sBest[3][q]));
        const float m1 = fminf(fminf(sBest[0][q + QUART_T], sBest[1][q + QUART_T]),
                               fminf(sBest[2][q + QUART_T], sBest[3][q + QUART_T]));
        // NN squared distance: max(xx + best, 0); clamp commutes with min.
        local = fmaxf(xx0 + m0, 0.0f) + fmaxf(xx1 + m1, 0.0f);
        local *= (1.0f / BQ);   // mean over batch of per-batch sums

        if (dir == 0) {
            // Fused EMD: cumsum over D=2 -> (t0-p0)^2 + (t0+t1-p0-p1)^2
            const float* tb = yt + (size_t)b * NPTS * 2;
            const float* pb = yp + (size_t)b * NPTS * 2;
            float e = 0.0f;
            const float2 t0v = reinterpret_cast<const float2*>(tb)[i0];
            const float2 p0v = reinterpret_cast<const float2*>(pb)[i0];
            const float2 t1v = reinterpret_cast<const float2*>(tb)[i1];
            const float2 p1v = reinterpret_cast<const float2*>(pb)[i1];
            float d0 = t0v.x - p0v.x;
            float d1 = (t0v.x + t0v.y) - (p0v.x + p0v.y);
            e = fmaf(d0, d0, e); e = fmaf(d1, d1, e);
            d0 = t1v.x - p1v.x;
            d1 = (t1v.x + t1v.y) - (p1v.x + p1v.y);
            e = fmaf(d0, d0, e); e = fmaf(d1, d1, e);
            local += e * (1.0f / ((float)BQ * NPTS * 2));
        }
    }

    // Deterministic block tree reduction over all 1024 threads.
    red[tid] = local;
    __syncthreads();
    for (int s = THREADS / 2; s > 0; s >>= 1) {
        if (tid < s) red[tid] += red[tid + s];
        __syncthreads();
    }
    const int bid = (blockIdx.z * gridDim.y + blockIdx.y) * gridDim.x + blockIdx.x;
    if (tid == 0) {
        g_partials[bid] = red[0];
        __threadfence();
        const int c = atomicAdd(&g_counter, 1);
        isLast = (c == NBLOCKS - 1);
    }
    __syncthreads();

    // Last block: deterministic fixed-order final sum of the 128 partials.
    if (isLast) {
        float v = 0.0f;
        if (tid < NBLOCKS) {
            __threadfence();
            v = *((volatile float*)&g_partials[tid]);
        }
        red[tid] = v;
        __syncthreads();
        for (int s = THREADS / 2; s > 0; s >>= 1) {
            if (tid < s) red[tid] += red[tid + s];
            __syncthreads();
        }
        if (tid == 0) {
            out[0] = red[0];
            g_counter = 0;   // reset for next graph replay
        }
    }
}

extern "C" void kernel_launch(void* const* d_in, const int* in_sizes, int n_in,
                              void* d_out, int out_size) {
    const float* y_true = (const float*)d_in[0];
    const float* y_pred = (const float*)d_in[1];
    float* out = (float*)d_out;

    dim3 grid(NTILES, BQ, 2);
    chamfer_kernel<<<grid, THREADS>>>(y_true, y_pred, out);
}